// round 3
// baseline (speedup 1.0000x reference)
#include <cuda_runtime.h>

#define NB 16
#define NC 512
#define NN 1024
#define NH 8
#define ND 64

// Scratch (device globals: allocation-free per harness rules)
__device__ float g_q[(size_t)NB * NC * NN];
__device__ float g_k[(size_t)NB * NC * NN];
__device__ float g_v[(size_t)NB * NC * NN];
__device__ float g_pos[(size_t)NC * NN];   // [head*d][N]

// pos[h,d,n] = rel_h[h,d,hc] + rel_w[h,d,w],  n = w*32 + hc
__global__ void pos_kernel(const float* __restrict__ rel_h,
                           const float* __restrict__ rel_w) {
    int idx = blockIdx.x * blockDim.x + threadIdx.x;
    if (idx >= NC * NN) return;
    int hd = idx / NN, n = idx % NN;
    int w = n >> 5, hc = n & 31;
    g_pos[idx] = rel_h[hd * 32 + hc] + rel_w[hd * 32 + w];
}

// out[b][o][n] = sum_c W[o][c] x[b][c][n] + bias[o]
// grid: (N/64, C/64, B*3), 256 threads, 4x4 per thread
__global__ __launch_bounds__(256) void qkv_kernel(
    const float* __restrict__ x,
    const float* __restrict__ Wq, const float* __restrict__ bq,
    const float* __restrict__ Wk, const float* __restrict__ bk,
    const float* __restrict__ Wv, const float* __restrict__ bv)
{
    __shared__ float Ws[16][68];  // [c][o] (transposed tile)
    __shared__ float Xs[16][68];  // [c][n]

    int which = blockIdx.z % 3;
    int b     = blockIdx.z / 3;
    const float* Wm   = (which == 0) ? Wq : (which == 1) ? Wk : Wv;
    const float* bias = (which == 0) ? bq : (which == 1) ? bk : bv;
    float*       out  = (which == 0) ? g_q : (which == 1) ? g_k : g_v;

    int oT = blockIdx.y * 64;
    int nT = blockIdx.x * 64;
    int tid = threadIdx.x;
    int ty = tid >> 4, tx = tid & 15;

    const float* xb = x + (size_t)b * NC * NN;
    float acc[4][4] = {};

    int wr = tid >> 2;            // 0..63 (o within tile)
    int wc = (tid & 3) * 4;       // 0..12 (c within tile)
    int xr = tid >> 4;            // 0..15 (c within tile)
    int xc = (tid & 15) * 4;      // 0..60 (n within tile)

    for (int ct = 0; ct < NC; ct += 16) {
        float4 wv = *(const float4*)&Wm[(size_t)(oT + wr) * NC + ct + wc];
        Ws[wc + 0][wr] = wv.x;
        Ws[wc + 1][wr] = wv.y;
        Ws[wc + 2][wr] = wv.z;
        Ws[wc + 3][wr] = wv.w;
        *(float4*)&Xs[xr][xc] = *(const float4*)&xb[(size_t)(ct + xr) * NN + nT + xc];
        __syncthreads();
        #pragma unroll
        for (int kk = 0; kk < 16; kk++) {
            float4 a = *(float4*)&Ws[kk][ty * 4];
            float4 v4 = *(float4*)&Xs[kk][tx * 4];
            acc[0][0] += a.x * v4.x; acc[0][1] += a.x * v4.y; acc[0][2] += a.x * v4.z; acc[0][3] += a.x * v4.w;
            acc[1][0] += a.y * v4.x; acc[1][1] += a.y * v4.y; acc[1][2] += a.y * v4.z; acc[1][3] += a.y * v4.w;
            acc[2][0] += a.z * v4.x; acc[2][1] += a.z * v4.y; acc[2][2] += a.z * v4.z; acc[2][3] += a.z * v4.w;
            acc[3][0] += a.w * v4.x; acc[3][1] += a.w * v4.y; acc[3][2] += a.w * v4.z; acc[3][3] += a.w * v4.w;
        }
        __syncthreads();
    }
    #pragma unroll
    for (int u = 0; u < 4; u++) {
        float bi = bias[oT + ty * 4 + u];
        float4 r;
        r.x = acc[u][0] + bi; r.y = acc[u][1] + bi; r.z = acc[u][2] + bi; r.w = acc[u][3] + bi;
        *(float4*)&out[((size_t)b * NC + oT + ty * 4 + u) * NN + nT + tx * 4] = r;
    }
}

// Flash-style attention per (b, h, query-tile of 64).
// Q'[128,i] = [q ; pos], K'[128,j] = [k ; q], V[64,j].
// No online max (scores bounded ~|32|): P = exp(S), O += P*V^T, normalize at end.
__global__ __launch_bounds__(256) void attn_kernel(const float* __restrict__ x,
                                                   float* __restrict__ out)
{
    extern __shared__ float sm[];
    float* Qs = sm;                 // [128][68]
    float* KP = sm + 128 * 68;      // [128][68] K' tile; reused as P [64 j][68 i]
    float* Vs = sm + 2 * 128 * 68;  // [64 j][68 dd]

    int b = blockIdx.z, h = blockIdx.y;
    int i0 = blockIdx.x * 64;
    int tid = threadIdx.x;
    int ty = tid >> 4, tx = tid & 15;

    const float* qb = g_q + ((size_t)b * NC + h * ND) * NN;
    const float* kb = g_k + ((size_t)b * NC + h * ND) * NN;
    const float* vb = g_v + ((size_t)b * NC + h * ND) * NN;
    const float* pb = g_pos + (size_t)h * ND * NN;

    // Load Q' tile [128][64]
    for (int idx = tid; idx < 128 * 64; idx += 256) {
        int r = idx >> 6, cL = idx & 63;
        float val = (r < 64) ? qb[r * NN + i0 + cL] : pb[(r - 64) * NN + i0 + cL];
        Qs[r * 68 + cL] = val;
    }

    float accO[4][4] = {};
    float rowsum[4] = {};

    for (int jt = 0; jt < 16; jt++) {
        int j0 = jt * 64;
        for (int idx = tid; idx < 128 * 64; idx += 256) {
            int r = idx >> 6, cL = idx & 63;
            float val = (r < 64) ? kb[r * NN + j0 + cL] : qb[(r - 64) * NN + j0 + cL];
            KP[r * 68 + cL] = val;
        }
        for (int idx = tid; idx < 64 * 64; idx += 256) {
            int dd = idx >> 6, j = idx & 63;
            Vs[j * 68 + dd] = vb[dd * NN + j0 + j];
        }
        __syncthreads();

        // S[4][4] = Q'^T K' over 128 dims
        float S[4][4] = {};
        #pragma unroll 8
        for (int kk = 0; kk < 128; kk++) {
            float4 qv = *(float4*)&Qs[kk * 68 + ty * 4];
            float4 kv = *(float4*)&KP[kk * 68 + tx * 4];
            S[0][0] += qv.x * kv.x; S[0][1] += qv.x * kv.y; S[0][2] += qv.x * kv.z; S[0][3] += qv.x * kv.w;
            S[1][0] += qv.y * kv.x; S[1][1] += qv.y * kv.y; S[1][2] += qv.y * kv.z; S[1][3] += qv.y * kv.w;
            S[2][0] += qv.z * kv.x; S[2][1] += qv.z * kv.y; S[2][2] += qv.z * kv.z; S[2][3] += qv.z * kv.w;
            S[3][0] += qv.w * kv.x; S[3][1] += qv.w * kv.y; S[3][2] += qv.w * kv.z; S[3][3] += qv.w * kv.w;
        }
        __syncthreads();  // everyone done reading KP before P overwrites it

        float rs[4];
        #pragma unroll
        for (int u = 0; u < 4; u++) {
            #pragma unroll
            for (int v = 0; v < 4; v++) S[u][v] = __expf(S[u][v]);
            rs[u] = S[u][0] + S[u][1] + S[u][2] + S[u][3];
        }
        // P -> KP as [j][i]
        #pragma unroll
        for (int v = 0; v < 4; v++)
            #pragma unroll
            for (int u = 0; u < 4; u++)
                KP[(tx * 4 + v) * 68 + ty * 4 + u] = S[u][v];
        // reduce row sums across the 16 tx lanes
        #pragma unroll
        for (int off = 1; off < 16; off <<= 1)
            #pragma unroll
            for (int u = 0; u < 4; u++)
                rs[u] += __shfl_xor_sync(0xffffffffu, rs[u], off, 16);
        #pragma unroll
        for (int u = 0; u < 4; u++) rowsum[u] += rs[u];
        __syncthreads();  // P visible

        // O[i][dd] += sum_j P[j][i] * V[j][dd]
        #pragma unroll 8
        for (int j = 0; j < 64; j++) {
            float4 vv = *(float4*)&Vs[j * 68 + tx * 4];
            float p0 = KP[j * 68 + ty * 4 + 0];
            float p1 = KP[j * 68 + ty * 4 + 1];
            float p2 = KP[j * 68 + ty * 4 + 2];
            float p3 = KP[j * 68 + ty * 4 + 3];
            accO[0][0] += p0 * vv.x; accO[0][1] += p0 * vv.y; accO[0][2] += p0 * vv.z; accO[0][3] += p0 * vv.w;
            accO[1][0] += p1 * vv.x; accO[1][1] += p1 * vv.y; accO[1][2] += p1 * vv.z; accO[1][3] += p1 * vv.w;
            accO[2][0] += p2 * vv.x; accO[2][1] += p2 * vv.y; accO[2][2] += p2 * vv.z; accO[2][3] += p2 * vv.w;
            accO[3][0] += p3 * vv.x; accO[3][1] += p3 * vv.y; accO[3][2] += p3 * vv.z; accO[3][3] += p3 * vv.w;
        }
        __syncthreads();  // done with KP/Vs before next tile load
    }

    // Normalize and write (via smem transpose to get coalesced [c][n] writes)
    float inv[4];
    #pragma unroll
    for (int u = 0; u < 4; u++) inv[u] = 1.0f / rowsum[u];
    #pragma unroll
    for (int v = 0; v < 4; v++)
        #pragma unroll
        for (int u = 0; u < 4; u++)
            Qs[(tx * 4 + v) * 68 + ty * 4 + u] = accO[u][v] * inv[u];  // Os[dd][i]
    __syncthreads();

    const float* xb = x + ((size_t)b * NC + h * ND) * NN;
    float*       ob = out + ((size_t)b * NC + h * ND) * NN;
    for (int idx = tid; idx < 64 * 64; idx += 256) {
        int dd = idx >> 6, iL = idx & 63;
        ob[dd * NN + i0 + iL] = Qs[dd * 68 + iL] + xb[dd * NN + i0 + iL];
    }
}

extern "C" void kernel_launch(void* const* d_in, const int* in_sizes, int n_in,
                              void* d_out, int out_size) {
    (void)in_sizes; (void)n_in; (void)out_size;
    const float* x     = (const float*)d_in[0];
    const float* Wq    = (const float*)d_in[1];
    const float* bq    = (const float*)d_in[2];
    const float* Wk    = (const float*)d_in[3];
    const float* bk    = (const float*)d_in[4];
    const float* Wv    = (const float*)d_in[5];
    const float* bv    = (const float*)d_in[6];
    const float* rel_h = (const float*)d_in[7];
    const float* rel_w = (const float*)d_in[8];
    // d_in[9] (reg_qk) and d_in[10] (reg_v) are provably dead: the reg group is
    // sliced away by out[:, :head] and softmax/PV are group-independent.
    float* out = (float*)d_out;

    cudaFuncSetAttribute(attn_kernel, cudaFuncAttributeMaxDynamicSharedMemorySize,
                         320 * 68 * 4);

    pos_kernel<<<(NC * NN + 255) / 256, 256>>>(rel_h, rel_w);
    qkv_kernel<<<dim3(NN / 64, NC / 64, NB * 3), 256>>>(x, Wq, bq, Wk, bk, Wv, bv);
    attn_kernel<<<dim3(NN / 64, NH, NB), 256, 320 * 68 * 4>>>(x, out);
}

// round 6
// speedup vs baseline: 3.9355x; 3.9355x over previous
#include <cuda_runtime.h>
#include <cuda_bf16.h>
#include <cstdint>

#define NB 16
#define NC 512
#define NN 1024
#define NH 8
#define ND 64

// ---------------- scratch (device globals; allocation-free) ----------------
__device__ __align__(16) __nv_bfloat16 g_q_hi[(size_t)NB*NC*NN];
__device__ __align__(16) __nv_bfloat16 g_q_lo[(size_t)NB*NC*NN];
__device__ __align__(16) __nv_bfloat16 g_k_hi[(size_t)NB*NC*NN];
__device__ __align__(16) __nv_bfloat16 g_k_lo[(size_t)NB*NC*NN];
__device__ __align__(16) __nv_bfloat16 g_v_hi[(size_t)NB*NC*NN];
__device__ __align__(16) __nv_bfloat16 g_v_lo[(size_t)NB*NC*NN];
__device__ __align__(16) __nv_bfloat16 g_x_hi[(size_t)NB*NC*NN];
__device__ __align__(16) __nv_bfloat16 g_x_lo[(size_t)NB*NC*NN];
__device__ __align__(16) __nv_bfloat16 g_w_hi[(size_t)3*NC*NC];
__device__ __align__(16) __nv_bfloat16 g_w_lo[(size_t)3*NC*NC];
__device__ __align__(16) __nv_bfloat16 g_pos_hi[(size_t)NC*NN];
__device__ __align__(16) __nv_bfloat16 g_pos_lo[(size_t)NC*NN];

// ---------------- helpers ----------------
__device__ __forceinline__ void cp16(uint32_t dst, const void* src){
    asm volatile("cp.async.cg.shared.global [%0], [%1], 16;" :: "r"(dst), "l"(src));
}
__device__ __forceinline__ void cp_commit(){ asm volatile("cp.async.commit_group;"); }
template<int N> __device__ __forceinline__ void cp_wait(){
    asm volatile("cp.async.wait_group %0;" :: "n"(N));
}
__device__ __forceinline__ void ldsm4(uint32_t r[4], uint32_t a){
    asm volatile("ldmatrix.sync.aligned.m8n8.x4.shared.b16 {%0,%1,%2,%3},[%4];"
        : "=r"(r[0]),"=r"(r[1]),"=r"(r[2]),"=r"(r[3]) : "r"(a));
}
__device__ __forceinline__ void ldsm4t(uint32_t r[4], uint32_t a){
    asm volatile("ldmatrix.sync.aligned.m8n8.x4.trans.shared.b16 {%0,%1,%2,%3},[%4];"
        : "=r"(r[0]),"=r"(r[1]),"=r"(r[2]),"=r"(r[3]) : "r"(a));
}
__device__ __forceinline__ void ldsm2t(uint32_t r[2], uint32_t a){
    asm volatile("ldmatrix.sync.aligned.m8n8.x2.trans.shared.b16 {%0,%1},[%2];"
        : "=r"(r[0]),"=r"(r[1]) : "r"(a));
}
__device__ __forceinline__ void ldsm2(uint32_t r[2], uint32_t a){
    asm volatile("ldmatrix.sync.aligned.m8n8.x2.shared.b16 {%0,%1},[%2];"
        : "=r"(r[0]),"=r"(r[1]) : "r"(a));
}
__device__ __forceinline__ void mma_bf16(float* c, const uint32_t* a, const uint32_t* b){
    asm volatile("mma.sync.aligned.m16n8k16.row.col.f32.bf16.bf16.f32 "
        "{%0,%1,%2,%3},{%4,%5,%6,%7},{%8,%9},{%0,%1,%2,%3};"
        : "+f"(c[0]),"+f"(c[1]),"+f"(c[2]),"+f"(c[3])
        : "r"(a[0]),"r"(a[1]),"r"(a[2]),"r"(a[3]),"r"(b[0]),"r"(b[1]));
}
__device__ __forceinline__ uint32_t packbf(__nv_bfloat16 x, __nv_bfloat16 y){
    __nv_bfloat162 t; t.x = x; t.y = y;
    return *reinterpret_cast<uint32_t*>(&t);
}
__device__ __forceinline__ void split2(float x, float y, uint32_t& h, uint32_t& l){
    __nv_bfloat16 hx = __float2bfloat16(x), hy = __float2bfloat16(y);
    h = packbf(hx, hy);
    l = packbf(__float2bfloat16(x - __bfloat162float(hx)),
               __float2bfloat16(y - __bfloat162float(hy)));
}
__device__ __forceinline__ void store_pair(__nv_bfloat16* hi, __nv_bfloat16* lo,
                                           size_t off, float x, float y){
    __nv_bfloat16 hx = __float2bfloat16(x), hy = __float2bfloat16(y);
    __nv_bfloat162 H; H.x = hx; H.y = hy;
    __nv_bfloat162 L;
    L.x = __float2bfloat16(x - __bfloat162float(hx));
    L.y = __float2bfloat16(y - __bfloat162float(hy));
    *reinterpret_cast<__nv_bfloat162*>(hi + off) = H;
    *reinterpret_cast<__nv_bfloat162*>(lo + off) = L;
}

// ---------------- split fp32 -> bf16 hi/lo ----------------
__global__ void split_kernel(const float* __restrict__ s, int sel, size_t off, int n4){
    int i = blockIdx.x * blockDim.x + threadIdx.x;
    if (i >= n4) return;
    __nv_bfloat16* hi = (sel == 0) ? g_x_hi : (g_w_hi + off);
    __nv_bfloat16* lo = (sel == 0) ? g_x_lo : (g_w_lo + off);
    float4 v = reinterpret_cast<const float4*>(s)[i];
    store_pair(hi, lo, (size_t)4*i + 0, v.x, v.y);
    store_pair(hi, lo, (size_t)4*i + 2, v.z, v.w);
}

__global__ void pos_split_kernel(const float* __restrict__ rel_h,
                                 const float* __restrict__ rel_w){
    int idx = blockIdx.x * blockDim.x + threadIdx.x;
    if (idx >= NC*NN) return;
    int hd = idx >> 10, n = idx & 1023;
    float v = rel_h[hd*32 + (n & 31)] + rel_w[hd*32 + (n >> 5)];
    __nv_bfloat16 h = __float2bfloat16(v);
    g_pos_hi[idx] = h;
    g_pos_lo[idx] = __float2bfloat16(v - __bfloat162float(h));
}

// ---------------- QKV GEMM: out[b][o][n] = sum_c W[o][c] x[b][c][n] + bias ----------------
// 128(o) x 128(n) tile, k-step 32, bf16 3-term split, cp.async double buffer. 64KB smem.
__global__ __launch_bounds__(256) void qkv_mma_kernel(
    const float* __restrict__ bq, const float* __restrict__ bk,
    const float* __restrict__ bv)
{
    extern __shared__ uint4 smemraw[];
    const uint32_t sbase = (uint32_t)__cvta_generic_to_shared(smemraw);
    const int tid = threadIdx.x, lane = tid & 31, warp = tid >> 5;
    const int wm = warp >> 2, wn = warp & 3;
    const int which = blockIdx.z % 3;
    const int b = blockIdx.z / 3;
    const int oT = blockIdx.y * 128, nT = blockIdx.x * 128;

    const __nv_bfloat16* Whi = g_w_hi + (size_t)which*NC*NC;
    const __nv_bfloat16* Wlo = g_w_lo + (size_t)which*NC*NC;
    const __nv_bfloat16* Xhi = g_x_hi + (size_t)b*NC*NN;
    const __nv_bfloat16* Xlo = g_x_lo + (size_t)b*NC*NN;
    const float* bias = (which==0) ? bq : (which==1) ? bk : bv;
    __nv_bfloat16* Ohi = (which==0) ? g_q_hi : (which==1) ? g_k_hi : g_v_hi;
    __nv_bfloat16* Olo = (which==0) ? g_q_lo : (which==1) ? g_k_lo : g_v_lo;

    auto aAddr = [&](int buf,int hl,int row,int u)->uint32_t{
        return sbase + (uint32_t)(((((buf<<1)+hl)<<7) + row)*4 + (u ^ ((row>>1)&3)))*16u; };
    auto bAddr = [&](int buf,int hl,int row,int u)->uint32_t{
        return sbase + (uint32_t)(2048 + ((((buf<<1)+hl)<<5) + row)*16 + (u ^ (row&7)))*16u; };

    auto issue = [&](int ct, int buf){
        #pragma unroll
        for (int hl = 0; hl < 2; hl++){
            const __nv_bfloat16* W = hl ? Wlo : Whi;
            const __nv_bfloat16* X = hl ? Xlo : Xhi;
            #pragma unroll
            for (int s = 0; s < 2; s++){
                int idx = tid + (s<<8);
                int row = idx >> 2, u = idx & 3;
                cp16(aAddr(buf,hl,row,u), W + (size_t)(oT+row)*NC + ct + u*8);
            }
            #pragma unroll
            for (int s = 0; s < 2; s++){
                int idx = tid + (s<<8);
                int row = idx >> 4, u = idx & 15;
                cp16(bAddr(buf,hl,row,u), X + (size_t)(ct+row)*NN + nT + u*8);
            }
        }
    };

    float C[4][4][4];
    #pragma unroll
    for (int a=0;a<4;a++)
        #pragma unroll
        for (int bb=0;bb<4;bb++)
            #pragma unroll
            for (int c=0;c<4;c++) C[a][bb][c]=0.f;

    issue(0, 0); cp_commit();
    for (int it = 0; it < 16; it++){
        if (it < 15){ issue((it+1)*32, (it+1)&1); cp_commit(); cp_wait<1>(); }
        else        { cp_wait<0>(); }
        __syncthreads();
        int buf = it & 1;
        #pragma unroll
        for (int k16 = 0; k16 < 2; k16++){
            int kk = k16 << 4;
            uint32_t ah[4][4], al[4][4], bh[4][2], bl[4][2];
            #pragma unroll
            for (int mi = 0; mi < 4; mi++){
                int row = wm*64 + mi*16 + (lane & 15);
                int kg  = (kk >> 3) + (lane >> 4);
                ldsm4(ah[mi], aAddr(buf,0,row,kg));
                ldsm4(al[mi], aAddr(buf,1,row,kg));
            }
            #pragma unroll
            for (int ni = 0; ni < 4; ni++){
                int row = kk + (lane & 15);
                int u = wn*4 + ni;
                ldsm2t(bh[ni], bAddr(buf,0,row,u));
                ldsm2t(bl[ni], bAddr(buf,1,row,u));
            }
            #pragma unroll
            for (int mi = 0; mi < 4; mi++)
                #pragma unroll
                for (int ni = 0; ni < 4; ni++){
                    mma_bf16(C[mi][ni], ah[mi], bh[ni]);
                    mma_bf16(C[mi][ni], ah[mi], bl[ni]);
                    mma_bf16(C[mi][ni], al[mi], bh[ni]);
                }
        }
        __syncthreads();
    }
    #pragma unroll
    for (int mi = 0; mi < 4; mi++){
        int r0 = oT + wm*64 + mi*16 + (lane >> 2);
        float bi0 = bias[r0], bi1 = bias[r0 + 8];
        #pragma unroll
        for (int ni = 0; ni < 4; ni++){
            int c0 = nT + wn*32 + ni*8 + (lane & 3)*2;
            size_t o0 = ((size_t)b*NC + r0)*NN + c0;
            store_pair(Ohi, Olo, o0,        C[mi][ni][0]+bi0, C[mi][ni][1]+bi0);
            store_pair(Ohi, Olo, o0 + 8*NN, C[mi][ni][2]+bi1, C[mi][ni][3]+bi1);
        }
    }
}

// ---------------- attention: flash-style, BM=128 i, BN=64 j, 8 warps (4 wm x 2 wn) ----------------
// smem 16B-units: Q' hi [0,2048) lo [2048,4096); K' 4096+hl*2048+buf*1024+row*8+u;
// V 8192+hl*1024+buf*512+row*8+u.  Total 10240 units = 160KB.
__global__ __launch_bounds__(256, 1) void attn_mma_kernel(const float* __restrict__ x,
                                                          float* __restrict__ out)
{
    extern __shared__ uint4 smemraw[];
    const uint32_t sbase = (uint32_t)__cvta_generic_to_shared(smemraw);
    float* smf = reinterpret_cast<float*>(smemraw);
    const int tid = threadIdx.x, lane = tid & 31, warp = tid >> 5;
    const int wm = warp >> 1, wn = warp & 1;
    const int b = blockIdx.z, h = blockIdx.y;
    const int i0 = blockIdx.x * 128;
    const size_t qoff = ((size_t)b*NC + h*ND)*NN;

    auto loadQ = [&](){
        #pragma unroll
        for (int s = 0; s < 16; s++){
            int idx = tid + s*256;
            int hl = idx >> 11, r = (idx >> 4) & 127, u = idx & 15;
            const __nv_bfloat16* src;
            if (r < 64) src = (hl ? g_q_lo : g_q_hi) + qoff + (size_t)r*NN + i0 + u*8;
            else src = (hl ? g_pos_lo : g_pos_hi) + ((size_t)h*ND + (r-64))*NN + i0 + u*8;
            cp16(sbase + (uint32_t)(hl*2048 + r*16 + (u ^ (r&7)))*16u, src);
        }
    };
    auto loadKV = [&](int jt, int buf){
        int j0 = jt * 64;
        #pragma unroll
        for (int s = 0; s < 8; s++){
            int idx = tid + s*256;
            int hl = idx >> 10, r = (idx >> 3) & 127, u = idx & 7;
            const __nv_bfloat16* src = (r < 64)
                ? (hl ? g_k_lo : g_k_hi) + qoff + (size_t)r*NN + j0 + u*8
                : (hl ? g_q_lo : g_q_hi) + qoff + (size_t)(r-64)*NN + j0 + u*8;
            cp16(sbase + (uint32_t)(4096 + hl*2048 + buf*1024 + r*8 + (u ^ (r&7)))*16u, src);
        }
        #pragma unroll
        for (int s = 0; s < 4; s++){
            int idx = tid + s*256;
            int hl = idx >> 9, r = (idx >> 3) & 63, u = idx & 7;
            const __nv_bfloat16* src = (hl ? g_v_lo : g_v_hi) + qoff + (size_t)r*NN + j0 + u*8;
            cp16(sbase + (uint32_t)(8192 + hl*1024 + buf*512 + r*8 + (u ^ (r&7)))*16u, src);
        }
    };

    float Oc[2][8][4];
    #pragma unroll
    for (int a=0;a<2;a++)
        #pragma unroll
        for (int bb=0;bb<8;bb++)
            #pragma unroll
            for (int c=0;c<4;c++) Oc[a][bb][c]=0.f;
    float rs[2][2] = {{0.f,0.f},{0.f,0.f}};

    loadQ(); loadKV(0, 0); cp_commit();

    for (int jt = 0; jt < 16; jt++){
        if (jt < 15){ loadKV(jt+1, (jt+1)&1); cp_commit(); cp_wait<1>(); }
        else        { cp_wait<0>(); }
        __syncthreads();
        int buf = jt & 1;

        // ---- S = Q'^T K' (k=128, 8 k16 steps, 3-term split) ----
        float S[2][4][4];
        #pragma unroll
        for (int a=0;a<2;a++)
            #pragma unroll
            for (int bb=0;bb<4;bb++)
                #pragma unroll
                for (int c=0;c<4;c++) S[a][bb][c]=0.f;

        #pragma unroll 2
        for (int k16 = 0; k16 < 8; k16++){
            uint32_t aH[2][4], aL[2][4], bH[4][2], bL[4][2];
            int arow = k16*16 + (lane & 7) + ((lane >> 4) << 3);
            #pragma unroll
            for (int mi = 0; mi < 2; mi++){
                int au = wm*4 + mi*2 + ((lane >> 3) & 1);
                uint32_t ad = sbase + (uint32_t)(arow*16 + (au ^ (arow&7)))*16u;
                ldsm4t(aH[mi], ad);
                ldsm4t(aL[mi], ad + 2048u*16u);
            }
            int brow = k16*16 + (lane & 15);
            #pragma unroll
            for (int ni = 0; ni < 4; ni++){
                int bu = wn*4 + ni;
                uint32_t bd = sbase + (uint32_t)(4096 + buf*1024 + brow*8 + (bu ^ (brow&7)))*16u;
                ldsm2t(bH[ni], bd);
                ldsm2t(bL[ni], bd + 2048u*16u);
            }
            #pragma unroll
            for (int mi = 0; mi < 2; mi++)
                #pragma unroll
                for (int ni = 0; ni < 4; ni++){
                    mma_bf16(S[mi][ni], aH[mi], bH[ni]);
                    mma_bf16(S[mi][ni], aH[mi], bL[ni]);
                    mma_bf16(S[mi][ni], aL[mi], bH[ni]);
                }
        }

        // ---- P = exp(S), partial rowsum ----
        #pragma unroll
        for (int mi = 0; mi < 2; mi++)
            #pragma unroll
            for (int ni = 0; ni < 4; ni++){
                #pragma unroll
                for (int c = 0; c < 4; c++) S[mi][ni][c] = __expf(S[mi][ni][c]);
                rs[mi][0] += S[mi][ni][0] + S[mi][ni][1];
                rs[mi][1] += S[mi][ni][2] + S[mi][ni][3];
            }

        // ---- O += P V^T (P in regs as A-fragments; V from smem) ----
        #pragma unroll
        for (int kt = 0; kt < 2; kt++){
            uint32_t pH[2][4], pL[2][4];
            #pragma unroll
            for (int mi = 0; mi < 2; mi++){
                split2(S[mi][2*kt  ][0], S[mi][2*kt  ][1], pH[mi][0], pL[mi][0]);
                split2(S[mi][2*kt  ][2], S[mi][2*kt  ][3], pH[mi][1], pL[mi][1]);
                split2(S[mi][2*kt+1][0], S[mi][2*kt+1][1], pH[mi][2], pL[mi][2]);
                split2(S[mi][2*kt+1][2], S[mi][2*kt+1][3], pH[mi][3], pL[mi][3]);
            }
            #pragma unroll
            for (int nd = 0; nd < 8; nd++){
                int vrow = nd*8 + (lane & 7);
                int vu = wn*4 + kt*2 + ((lane >> 3) & 1);
                uint32_t vd = sbase + (uint32_t)(8192 + buf*512 + vrow*8 + (vu ^ (vrow&7)))*16u;
                uint32_t vH[2], vL[2];
                ldsm2(vH, vd);
                ldsm2(vL, vd + 1024u*16u);
                #pragma unroll
                for (int mi = 0; mi < 2; mi++){
                    mma_bf16(Oc[mi][nd], pH[mi], vH);
                    mma_bf16(Oc[mi][nd], pH[mi], vL);
                    mma_bf16(Oc[mi][nd], pL[mi], vH);
                }
            }
        }
        __syncthreads();
    }

    // ---- cross-warp (wn) reduction, normalize, +x, store ----
    float* Os = smf;                 // [128 i][65] fp32 (Q' region dead)
    float* rsum_s = smf + 128*65;
    #pragma unroll
    for (int off = 1; off < 4; off <<= 1)
        #pragma unroll
        for (int mi = 0; mi < 2; mi++){
            rs[mi][0] += __shfl_xor_sync(0xffffffffu, rs[mi][0], off);
            rs[mi][1] += __shfl_xor_sync(0xffffffffu, rs[mi][1], off);
        }
    if (wn == 0){
        #pragma unroll
        for (int mi = 0; mi < 2; mi++){
            int ib = wm*32 + mi*16 + (lane >> 2);
            #pragma unroll
            for (int nd = 0; nd < 8; nd++){
                int dd = nd*8 + (lane & 3)*2;
                Os[ib*65 + dd]       = Oc[mi][nd][0];
                Os[ib*65 + dd + 1]   = Oc[mi][nd][1];
                Os[(ib+8)*65 + dd]   = Oc[mi][nd][2];
                Os[(ib+8)*65 + dd+1] = Oc[mi][nd][3];
            }
            if ((lane & 3) == 0){ rsum_s[ib] = rs[mi][0]; rsum_s[ib+8] = rs[mi][1]; }
        }
    }
    __syncthreads();
    if (wn == 1){
        #pragma unroll
        for (int mi = 0; mi < 2; mi++){
            int ib = wm*32 + mi*16 + (lane >> 2);
            #pragma unroll
            for (int nd = 0; nd < 8; nd++){
                int dd = nd*8 + (lane & 3)*2;
                Os[ib*65 + dd]       += Oc[mi][nd][0];
                Os[ib*65 + dd + 1]   += Oc[mi][nd][1];
                Os[(ib+8)*65 + dd]   += Oc[mi][nd][2];
                Os[(ib+8)*65 + dd+1] += Oc[mi][nd][3];
            }
            if ((lane & 3) == 0){ rsum_s[ib] += rs[mi][0]; rsum_s[ib+8] += rs[mi][1]; }
        }
    }
    __syncthreads();
    if (tid < 128) rsum_s[tid] = 1.0f / rsum_s[tid];
    __syncthreads();

    const float* xb = x + qoff;
    float* ob = out + qoff;
    #pragma unroll
    for (int s = 0; s < 32; s++){
        int idx = tid + s*256;
        int dd = idx >> 7, iL = idx & 127;
        ob[(size_t)dd*NN + i0 + iL] =
            Os[iL*65 + dd] * rsum_s[iL] + xb[(size_t)dd*NN + i0 + iL];
    }
}

extern "C" void kernel_launch(void* const* d_in, const int* in_sizes, int n_in,
                              void* d_out, int out_size) {
    (void)in_sizes; (void)n_in; (void)out_size;
    const float* x     = (const float*)d_in[0];
    const float* Wq    = (const float*)d_in[1];
    const float* bq    = (const float*)d_in[2];
    const float* Wk    = (const float*)d_in[3];
    const float* bk    = (const float*)d_in[4];
    const float* Wv    = (const float*)d_in[5];
    const float* bv    = (const float*)d_in[6];
    const float* rel_h = (const float*)d_in[7];
    const float* rel_w = (const float*)d_in[8];
    // d_in[9]/d_in[10] (reg_qk/reg_v) are provably dead: the reg group is sliced
    // away by out[:, :head] and softmax/PV are group-independent.
    float* out = (float*)d_out;

    cudaFuncSetAttribute(qkv_mma_kernel,
        cudaFuncAttributeMaxDynamicSharedMemorySize, 65536);
    cudaFuncSetAttribute(attn_mma_kernel,
        cudaFuncAttributeMaxDynamicSharedMemorySize, 163840);

    split_kernel<<<8192, 256>>>(x,  0, 0, 2097152);
    split_kernel<<<256, 256>>>(Wq, 1, 0, 65536);
    split_kernel<<<256, 256>>>(Wk, 1, (size_t)NC*NC, 65536);
    split_kernel<<<256, 256>>>(Wv, 1, (size_t)2*NC*NC, 65536);
    pos_split_kernel<<<2048, 256>>>(rel_h, rel_w);
    qkv_mma_kernel<<<dim3(NN/128, NC/128, 3*NB), 256, 65536>>>(bq, bk, bv);
    attn_mma_kernel<<<dim3(NN/128, NH, NB), 256, 163840>>>(x, out);
}

// round 7
// speedup vs baseline: 8.2312x; 2.0915x over previous
#include <cuda_runtime.h>
#include <cuda_fp16.h>
#include <cstdint>

#define NB 16
#define NC 512
#define NN 1024
#define NH 8
#define ND 64

// ---------------- scratch (device globals; allocation-free) ----------------
__device__ __align__(16) __half g_qh[(size_t)NB*NC*NN];
__device__ __align__(16) __half g_kh[(size_t)NB*NC*NN];
__device__ __align__(16) __half g_vh[(size_t)NB*NC*NN];
__device__ __align__(16) __half g_xh[(size_t)NB*NC*NN];
__device__ __align__(16) __half g_wh[(size_t)3*NC*NC];
__device__ __align__(16) __half g_ph[(size_t)NC*NN];

// ---------------- helpers ----------------
__device__ __forceinline__ void cp16(uint32_t dst, const void* src){
    asm volatile("cp.async.cg.shared.global [%0], [%1], 16;" :: "r"(dst), "l"(src));
}
__device__ __forceinline__ void cp_commit(){ asm volatile("cp.async.commit_group;"); }
template<int N> __device__ __forceinline__ void cp_wait(){
    asm volatile("cp.async.wait_group %0;" :: "n"(N));
}
__device__ __forceinline__ void ldsm4(uint32_t r[4], uint32_t a){
    asm volatile("ldmatrix.sync.aligned.m8n8.x4.shared.b16 {%0,%1,%2,%3},[%4];"
        : "=r"(r[0]),"=r"(r[1]),"=r"(r[2]),"=r"(r[3]) : "r"(a));
}
__device__ __forceinline__ void ldsm4t(uint32_t r[4], uint32_t a){
    asm volatile("ldmatrix.sync.aligned.m8n8.x4.trans.shared.b16 {%0,%1,%2,%3},[%4];"
        : "=r"(r[0]),"=r"(r[1]),"=r"(r[2]),"=r"(r[3]) : "r"(a));
}
__device__ __forceinline__ void ldsm2t(uint32_t r[2], uint32_t a){
    asm volatile("ldmatrix.sync.aligned.m8n8.x2.trans.shared.b16 {%0,%1},[%2];"
        : "=r"(r[0]),"=r"(r[1]) : "r"(a));
}
__device__ __forceinline__ void ldsm2(uint32_t r[2], uint32_t a){
    asm volatile("ldmatrix.sync.aligned.m8n8.x2.shared.b16 {%0,%1},[%2];"
        : "=r"(r[0]),"=r"(r[1]) : "r"(a));
}
__device__ __forceinline__ void mma_f16(float* c, const uint32_t* a, const uint32_t* b){
    asm volatile("mma.sync.aligned.m16n8k16.row.col.f32.f16.f16.f32 "
        "{%0,%1,%2,%3},{%4,%5,%6,%7},{%8,%9},{%0,%1,%2,%3};"
        : "+f"(c[0]),"+f"(c[1]),"+f"(c[2]),"+f"(c[3])
        : "r"(a[0]),"r"(a[1]),"r"(a[2]),"r"(a[3]),"r"(b[0]),"r"(b[1]));
}
__device__ __forceinline__ uint32_t packh2(float x, float y){
    __half2 t = __floats2half2_rn(x, y);
    return *reinterpret_cast<uint32_t*>(&t);
}

// ---------------- convert fp32 -> fp16 ----------------
__global__ void cvt_kernel(const float* __restrict__ s, int sel, size_t off, int n4){
    int i = blockIdx.x * blockDim.x + threadIdx.x;
    if (i >= n4) return;
    __half* dst = sel ? (g_wh + off) : g_xh;
    float4 v = reinterpret_cast<const float4*>(s)[i];
    __half2* d2 = reinterpret_cast<__half2*>(dst + (size_t)4*i);
    d2[0] = __floats2half2_rn(v.x, v.y);
    d2[1] = __floats2half2_rn(v.z, v.w);
}

__global__ void pos_cvt_kernel(const float* __restrict__ rel_h,
                               const float* __restrict__ rel_w){
    int idx = blockIdx.x * blockDim.x + threadIdx.x;
    if (idx >= NC*NN) return;
    int hd = idx >> 10, n = idx & 1023;
    g_ph[idx] = __float2half(rel_h[hd*32 + (n & 31)] + rel_w[hd*32 + (n >> 5)]);
}

// ---------------- QKV GEMM: out[b][o][n] = sum_c W[o][c] x[b][c][n] + bias ----------------
// 128(o) x 128(n) tile, k-step 32, fp16 single-term, cp.async double buffer. 32KB smem.
__global__ __launch_bounds__(256) void qkv_mma_kernel(
    const float* __restrict__ bq, const float* __restrict__ bk,
    const float* __restrict__ bv)
{
    extern __shared__ uint4 smemraw[];
    const uint32_t sbase = (uint32_t)__cvta_generic_to_shared(smemraw);
    const int tid = threadIdx.x, lane = tid & 31, warp = tid >> 5;
    const int wm = warp >> 2, wn = warp & 3;
    const int which = blockIdx.z % 3;
    const int b = blockIdx.z / 3;
    const int oT = blockIdx.y * 128, nT = blockIdx.x * 128;

    const __half* Wh = g_wh + (size_t)which*NC*NC;
    const __half* Xh = g_xh + (size_t)b*NC*NN;
    const float* bias = (which==0) ? bq : (which==1) ? bk : bv;
    __half* Oh = (which==0) ? g_qh : (which==1) ? g_kh : g_vh;

    auto aAddr = [&](int buf,int row,int u)->uint32_t{
        return sbase + (uint32_t)(buf*512 + row*4 + (u ^ ((row>>1)&3)))*16u; };
    auto bAddr = [&](int buf,int row,int u)->uint32_t{
        return sbase + (uint32_t)(1024 + buf*512 + row*16 + (u ^ (row&7)))*16u; };

    auto issue = [&](int ct, int buf){
        #pragma unroll
        for (int s = 0; s < 2; s++){
            int idx = tid + (s<<8);
            int row = idx >> 2, u = idx & 3;
            cp16(aAddr(buf,row,u), Wh + (size_t)(oT+row)*NC + ct + u*8);
        }
        #pragma unroll
        for (int s = 0; s < 2; s++){
            int idx = tid + (s<<8);
            int row = idx >> 4, u = idx & 15;
            cp16(bAddr(buf,row,u), Xh + (size_t)(ct+row)*NN + nT + u*8);
        }
    };

    float C[4][4][4];
    #pragma unroll
    for (int a=0;a<4;a++)
        #pragma unroll
        for (int bb=0;bb<4;bb++)
            #pragma unroll
            for (int c=0;c<4;c++) C[a][bb][c]=0.f;

    issue(0, 0); cp_commit();
    for (int it = 0; it < 16; it++){
        if (it < 15){ issue((it+1)*32, (it+1)&1); cp_commit(); cp_wait<1>(); }
        else        { cp_wait<0>(); }
        __syncthreads();
        int buf = it & 1;
        #pragma unroll
        for (int k16 = 0; k16 < 2; k16++){
            int kk = k16 << 4;
            uint32_t ah[4][4], bh[4][2];
            #pragma unroll
            for (int mi = 0; mi < 4; mi++){
                int row = wm*64 + mi*16 + (lane & 15);
                int kg  = (kk >> 3) + (lane >> 4);
                ldsm4(ah[mi], aAddr(buf,row,kg));
            }
            #pragma unroll
            for (int ni = 0; ni < 4; ni++){
                int row = kk + (lane & 15);
                int u = wn*4 + ni;
                ldsm2t(bh[ni], bAddr(buf,row,u));
            }
            #pragma unroll
            for (int mi = 0; mi < 4; mi++)
                #pragma unroll
                for (int ni = 0; ni < 4; ni++)
                    mma_f16(C[mi][ni], ah[mi], bh[ni]);
        }
        __syncthreads();
    }
    #pragma unroll
    for (int mi = 0; mi < 4; mi++){
        int r0 = oT + wm*64 + mi*16 + (lane >> 2);
        float bi0 = bias[r0], bi1 = bias[r0 + 8];
        #pragma unroll
        for (int ni = 0; ni < 4; ni++){
            int c0 = nT + wn*32 + ni*8 + (lane & 3)*2;
            size_t o0 = ((size_t)b*NC + r0)*NN + c0;
            *reinterpret_cast<__half2*>(Oh + o0) =
                __floats2half2_rn(C[mi][ni][0]+bi0, C[mi][ni][1]+bi0);
            *reinterpret_cast<__half2*>(Oh + o0 + (size_t)8*NN) =
                __floats2half2_rn(C[mi][ni][2]+bi1, C[mi][ni][3]+bi1);
        }
    }
}

// ---------------- attention: flash-style + online max, fp16, BM=128, BN=64 ----------------
// smem 16B-units: Q' [0,2048): r*16+(u^(r&7)); K' 2048+buf*1024+r*8+(u^(r&7));
// V 4096+buf*512+r*8+(u^(r&7)).  Total 5120 units = 80KB -> 2 CTAs/SM.
__global__ __launch_bounds__(256, 2) void attn_mma_kernel(const float* __restrict__ x,
                                                          float* __restrict__ out)
{
    extern __shared__ uint4 smemraw[];
    const uint32_t sbase = (uint32_t)__cvta_generic_to_shared(smemraw);
    float* smf = reinterpret_cast<float*>(smemraw);
    const int tid = threadIdx.x, lane = tid & 31, warp = tid >> 5;
    const int wm = warp >> 1, wn = warp & 1;
    const int b = blockIdx.z, h = blockIdx.y;
    const int i0 = blockIdx.x * 128;
    const size_t qoff = ((size_t)b*NC + h*ND)*NN;

    auto loadQ = [&](){
        #pragma unroll
        for (int s = 0; s < 8; s++){
            int idx = tid + s*256;
            int r = idx >> 4, u = idx & 15;
            const __half* src = (r < 64)
                ? g_qh + qoff + (size_t)r*NN + i0 + u*8
                : g_ph + ((size_t)h*ND + (r-64))*NN + i0 + u*8;
            cp16(sbase + (uint32_t)(r*16 + (u ^ (r&7)))*16u, src);
        }
    };
    auto loadKV = [&](int jt, int buf){
        int j0 = jt * 64;
        #pragma unroll
        for (int s = 0; s < 4; s++){
            int idx = tid + s*256;
            int r = idx >> 3, u = idx & 7;
            const __half* src = (r < 64)
                ? g_kh + qoff + (size_t)r*NN + j0 + u*8
                : g_qh + qoff + (size_t)(r-64)*NN + j0 + u*8;
            cp16(sbase + (uint32_t)(2048 + buf*1024 + r*8 + (u ^ (r&7)))*16u, src);
        }
        #pragma unroll
        for (int s = 0; s < 2; s++){
            int idx = tid + s*256;
            int r = idx >> 3, u = idx & 7;
            const __half* src = g_vh + qoff + (size_t)r*NN + j0 + u*8;
            cp16(sbase + (uint32_t)(4096 + buf*512 + r*8 + (u ^ (r&7)))*16u, src);
        }
    };

    float Oc[2][8][4];
    #pragma unroll
    for (int a=0;a<2;a++)
        #pragma unroll
        for (int bb=0;bb<8;bb++)
            #pragma unroll
            for (int c=0;c<4;c++) Oc[a][bb][c]=0.f;
    float rs[2][2] = {{0.f,0.f},{0.f,0.f}};
    float mr[2][2] = {{-1e30f,-1e30f},{-1e30f,-1e30f}};

    loadQ(); loadKV(0, 0); cp_commit();

    for (int jt = 0; jt < 16; jt++){
        if (jt < 15){ loadKV(jt+1, (jt+1)&1); cp_commit(); cp_wait<1>(); }
        else        { cp_wait<0>(); }
        __syncthreads();
        int buf = jt & 1;

        // ---- S = Q'^T K' (k=128, 8 k16 steps, fp16 single-term) ----
        float S[2][4][4];
        #pragma unroll
        for (int a=0;a<2;a++)
            #pragma unroll
            for (int bb=0;bb<4;bb++)
                #pragma unroll
                for (int c=0;c<4;c++) S[a][bb][c]=0.f;

        #pragma unroll
        for (int k16 = 0; k16 < 8; k16++){
            uint32_t aH[2][4], bH[4][2];
            int arow = k16*16 + (lane & 7) + ((lane >> 4) << 3);
            #pragma unroll
            for (int mi = 0; mi < 2; mi++){
                int au = wm*4 + mi*2 + ((lane >> 3) & 1);
                ldsm4t(aH[mi], sbase + (uint32_t)(arow*16 + (au ^ (arow&7)))*16u);
            }
            int brow = k16*16 + (lane & 15);
            #pragma unroll
            for (int ni = 0; ni < 4; ni++){
                int bu = wn*4 + ni;
                ldsm2t(bH[ni], sbase + (uint32_t)(2048 + buf*1024 + brow*8 + (bu ^ (brow&7)))*16u);
            }
            #pragma unroll
            for (int mi = 0; mi < 2; mi++)
                #pragma unroll
                for (int ni = 0; ni < 4; ni++)
                    mma_f16(S[mi][ni], aH[mi], bH[ni]);
        }

        // ---- online softmax (per-warp running max over its j-half) ----
        #pragma unroll
        for (int mi = 0; mi < 2; mi++){
            float t0 = -1e30f, t1 = -1e30f;
            #pragma unroll
            for (int ni = 0; ni < 4; ni++){
                t0 = fmaxf(t0, fmaxf(S[mi][ni][0], S[mi][ni][1]));
                t1 = fmaxf(t1, fmaxf(S[mi][ni][2], S[mi][ni][3]));
            }
            #pragma unroll
            for (int off = 1; off < 4; off <<= 1){
                t0 = fmaxf(t0, __shfl_xor_sync(0xffffffffu, t0, off));
                t1 = fmaxf(t1, __shfl_xor_sync(0xffffffffu, t1, off));
            }
            float nm0 = fmaxf(mr[mi][0], t0), nm1 = fmaxf(mr[mi][1], t1);
            float sc0 = __expf(mr[mi][0] - nm0), sc1 = __expf(mr[mi][1] - nm1);
            mr[mi][0] = nm0; mr[mi][1] = nm1;
            float ps0 = 0.f, ps1 = 0.f;
            #pragma unroll
            for (int ni = 0; ni < 4; ni++){
                S[mi][ni][0] = __expf(S[mi][ni][0] - nm0);
                S[mi][ni][1] = __expf(S[mi][ni][1] - nm0);
                S[mi][ni][2] = __expf(S[mi][ni][2] - nm1);
                S[mi][ni][3] = __expf(S[mi][ni][3] - nm1);
                ps0 += S[mi][ni][0] + S[mi][ni][1];
                ps1 += S[mi][ni][2] + S[mi][ni][3];
            }
            rs[mi][0] = rs[mi][0]*sc0 + ps0;
            rs[mi][1] = rs[mi][1]*sc1 + ps1;
            #pragma unroll
            for (int nd = 0; nd < 8; nd++){
                Oc[mi][nd][0] *= sc0; Oc[mi][nd][1] *= sc0;
                Oc[mi][nd][2] *= sc1; Oc[mi][nd][3] *= sc1;
            }
        }

        // ---- O += P V^T (P in regs as fp16 A-fragments; V from smem) ----
        #pragma unroll
        for (int kt = 0; kt < 2; kt++){
            uint32_t pF[2][4];
            #pragma unroll
            for (int mi = 0; mi < 2; mi++){
                pF[mi][0] = packh2(S[mi][2*kt  ][0], S[mi][2*kt  ][1]);
                pF[mi][1] = packh2(S[mi][2*kt  ][2], S[mi][2*kt  ][3]);
                pF[mi][2] = packh2(S[mi][2*kt+1][0], S[mi][2*kt+1][1]);
                pF[mi][3] = packh2(S[mi][2*kt+1][2], S[mi][2*kt+1][3]);
            }
            #pragma unroll
            for (int nd = 0; nd < 8; nd++){
                int vrow = nd*8 + (lane & 7);
                int vu = wn*4 + kt*2 + ((lane >> 3) & 1);
                uint32_t vF[2];
                ldsm2(vF, sbase + (uint32_t)(4096 + buf*512 + vrow*8 + (vu ^ (vrow&7)))*16u);
                #pragma unroll
                for (int mi = 0; mi < 2; mi++)
                    mma_f16(Oc[mi][nd], pF[mi], vF);
            }
        }
        __syncthreads();
    }

    // ---- cross-warp combine (max reconciliation), normalize, +x, store ----
    float* Os = smf;                   // [128 i][65] fp32 (tiles dead now)
    float* rsum_s = smf + 128*65;      // [128]
    float* mmax_s = rsum_s + 128;      // [128]
    #pragma unroll
    for (int off = 1; off < 4; off <<= 1)
        #pragma unroll
        for (int mi = 0; mi < 2; mi++){
            rs[mi][0] += __shfl_xor_sync(0xffffffffu, rs[mi][0], off);
            rs[mi][1] += __shfl_xor_sync(0xffffffffu, rs[mi][1], off);
        }
    if (wn == 0){
        #pragma unroll
        for (int mi = 0; mi < 2; mi++){
            int ib = wm*32 + mi*16 + (lane >> 2);
            #pragma unroll
            for (int nd = 0; nd < 8; nd++){
                int dd = nd*8 + (lane & 3)*2;
                Os[ib*65 + dd]       = Oc[mi][nd][0];
                Os[ib*65 + dd + 1]   = Oc[mi][nd][1];
                Os[(ib+8)*65 + dd]   = Oc[mi][nd][2];
                Os[(ib+8)*65 + dd+1] = Oc[mi][nd][3];
            }
            if ((lane & 3) == 0){
                rsum_s[ib]   = rs[mi][0]; rsum_s[ib+8] = rs[mi][1];
                mmax_s[ib]   = mr[mi][0]; mmax_s[ib+8] = mr[mi][1];
            }
        }
    }
    __syncthreads();
    if (wn == 1){
        #pragma unroll
        for (int mi = 0; mi < 2; mi++){
            int ib = wm*32 + mi*16 + (lane >> 2);
            float m0a = mmax_s[ib], m0b = mmax_s[ib+8];
            float Ma = fmaxf(m0a, mr[mi][0]), Mb = fmaxf(m0b, mr[mi][1]);
            float s0a = __expf(m0a - Ma), s1a = __expf(mr[mi][0] - Ma);
            float s0b = __expf(m0b - Mb), s1b = __expf(mr[mi][1] - Mb);
            #pragma unroll
            for (int nd = 0; nd < 8; nd++){
                int dd = nd*8 + (lane & 3)*2;
                Os[ib*65 + dd]       = Os[ib*65 + dd]      *s0a + Oc[mi][nd][0]*s1a;
                Os[ib*65 + dd + 1]   = Os[ib*65 + dd + 1]  *s0a + Oc[mi][nd][1]*s1a;
                Os[(ib+8)*65 + dd]   = Os[(ib+8)*65 + dd]  *s0b + Oc[mi][nd][2]*s1b;
                Os[(ib+8)*65 + dd+1] = Os[(ib+8)*65 + dd+1]*s0b + Oc[mi][nd][3]*s1b;
            }
            if ((lane & 3) == 0){
                rsum_s[ib]   = rsum_s[ib]  *s0a + rs[mi][0]*s1a;
                rsum_s[ib+8] = rsum_s[ib+8]*s0b + rs[mi][1]*s1b;
            }
        }
    }
    __syncthreads();
    if (tid < 128) rsum_s[tid] = 1.0f / rsum_s[tid];
    __syncthreads();

    const float* xb = x + qoff;
    float* ob = out + qoff;
    #pragma unroll
    for (int s = 0; s < 32; s++){
        int idx = tid + s*256;
        int dd = idx >> 7, iL = idx & 127;
        ob[(size_t)dd*NN + i0 + iL] =
            Os[iL*65 + dd] * rsum_s[iL] + xb[(size_t)dd*NN + i0 + iL];
    }
}

extern "C" void kernel_launch(void* const* d_in, const int* in_sizes, int n_in,
                              void* d_out, int out_size) {
    (void)in_sizes; (void)n_in; (void)out_size;
    const float* x     = (const float*)d_in[0];
    const float* Wq    = (const float*)d_in[1];
    const float* bq    = (const float*)d_in[2];
    const float* Wk    = (const float*)d_in[3];
    const float* bk    = (const float*)d_in[4];
    const float* Wv    = (const float*)d_in[5];
    const float* bv    = (const float*)d_in[6];
    const float* rel_h = (const float*)d_in[7];
    const float* rel_w = (const float*)d_in[8];
    // d_in[9]/d_in[10] (reg_qk/reg_v) are provably dead: the reg group is sliced
    // away by out[:, :head] and softmax/PV are group-independent.
    float* out = (float*)d_out;

    cudaFuncSetAttribute(qkv_mma_kernel,
        cudaFuncAttributeMaxDynamicSharedMemorySize, 32768);
    cudaFuncSetAttribute(attn_mma_kernel,
        cudaFuncAttributeMaxDynamicSharedMemorySize, 81920);

    cvt_kernel<<<8192, 256>>>(x,  0, 0, 2097152);
    cvt_kernel<<<256, 256>>>(Wq, 1, 0, 65536);
    cvt_kernel<<<256, 256>>>(Wk, 1, (size_t)NC*NC, 65536);
    cvt_kernel<<<256, 256>>>(Wv, 1, (size_t)2*NC*NC, 65536);
    pos_cvt_kernel<<<2048, 256>>>(rel_h, rel_w);
    qkv_mma_kernel<<<dim3(NN/128, NC/128, 3*NB), 256, 32768>>>(bq, bk, bv);
    attn_mma_kernel<<<dim3(NN/128, NH, NB), 256, 81920>>>(x, out);
}

// round 8
// speedup vs baseline: 8.2774x; 1.0056x over previous
#include <cuda_runtime.h>
#include <cuda_fp16.h>
#include <cstdint>

#define NB 16
#define NC 512
#define NN 1024
#define NH 8
#define ND 64

// ---------------- scratch (device globals; allocation-free) ----------------
__device__ __align__(16) __half g_qh[(size_t)NB*NC*NN];
__device__ __align__(16) __half g_kh[(size_t)NB*NC*NN];
__device__ __align__(16) __half g_vh[(size_t)NB*NC*NN];
__device__ __align__(16) __half g_xh[(size_t)NB*NC*NN];
__device__ __align__(16) __half g_wh[(size_t)3*NC*NC];
__device__ __align__(16) __half g_ph[(size_t)NC*NN];

// ---------------- helpers ----------------
__device__ __forceinline__ void cp16(uint32_t dst, const void* src){
    asm volatile("cp.async.cg.shared.global [%0], [%1], 16;" :: "r"(dst), "l"(src));
}
__device__ __forceinline__ void cp_commit(){ asm volatile("cp.async.commit_group;"); }
template<int N> __device__ __forceinline__ void cp_wait(){
    asm volatile("cp.async.wait_group %0;" :: "n"(N));
}
__device__ __forceinline__ void ldsm4(uint32_t r[4], uint32_t a){
    asm volatile("ldmatrix.sync.aligned.m8n8.x4.shared.b16 {%0,%1,%2,%3},[%4];"
        : "=r"(r[0]),"=r"(r[1]),"=r"(r[2]),"=r"(r[3]) : "r"(a));
}
__device__ __forceinline__ void ldsm4t(uint32_t r[4], uint32_t a){
    asm volatile("ldmatrix.sync.aligned.m8n8.x4.trans.shared.b16 {%0,%1,%2,%3},[%4];"
        : "=r"(r[0]),"=r"(r[1]),"=r"(r[2]),"=r"(r[3]) : "r"(a));
}
__device__ __forceinline__ void ldsm2t(uint32_t r[2], uint32_t a){
    asm volatile("ldmatrix.sync.aligned.m8n8.x2.trans.shared.b16 {%0,%1},[%2];"
        : "=r"(r[0]),"=r"(r[1]) : "r"(a));
}
__device__ __forceinline__ void ldsm2(uint32_t r[2], uint32_t a){
    asm volatile("ldmatrix.sync.aligned.m8n8.x2.shared.b16 {%0,%1},[%2];"
        : "=r"(r[0]),"=r"(r[1]) : "r"(a));
}
__device__ __forceinline__ void mma_f16(float* c, const uint32_t* a, const uint32_t* b){
    asm volatile("mma.sync.aligned.m16n8k16.row.col.f32.f16.f16.f32 "
        "{%0,%1,%2,%3},{%4,%5,%6,%7},{%8,%9},{%0,%1,%2,%3};"
        : "+f"(c[0]),"+f"(c[1]),"+f"(c[2]),"+f"(c[3])
        : "r"(a[0]),"r"(a[1]),"r"(a[2]),"r"(a[3]),"r"(b[0]),"r"(b[1]));
}
__device__ __forceinline__ uint32_t packh2(float x, float y){
    __half2 t = __floats2half2_rn(x, y);
    return *reinterpret_cast<uint32_t*>(&t);
}

// ---------------- convert fp32 -> fp16 ----------------
__global__ void cvt_kernel(const float* __restrict__ s, int sel, size_t off, int n4){
    int i = blockIdx.x * blockDim.x + threadIdx.x;
    if (i >= n4) return;
    __half* dst = sel ? (g_wh + off) : g_xh;
    float4 v = reinterpret_cast<const float4*>(s)[i];
    __half2* d2 = reinterpret_cast<__half2*>(dst + (size_t)4*i);
    d2[0] = __floats2half2_rn(v.x, v.y);
    d2[1] = __floats2half2_rn(v.z, v.w);
}

__global__ void pos_cvt_kernel(const float* __restrict__ rel_h,
                               const float* __restrict__ rel_w){
    int idx = blockIdx.x * blockDim.x + threadIdx.x;
    if (idx >= NC*NN) return;
    int hd = idx >> 10, n = idx & 1023;
    g_ph[idx] = __float2half(rel_h[hd*32 + (n & 31)] + rel_w[hd*32 + (n >> 5)]);
}

// ---------------- QKV GEMM: out[b][o][n] = sum_c W[o][c] x[b][c][n] + bias ----------------
// 128(o) x 128(n) tile, k-step 32, fp16 single-term, cp.async double buffer. 32KB smem.
__global__ __launch_bounds__(256) void qkv_mma_kernel(
    const float* __restrict__ bq, const float* __restrict__ bk,
    const float* __restrict__ bv)
{
    extern __shared__ uint4 smemraw[];
    const uint32_t sbase = (uint32_t)__cvta_generic_to_shared(smemraw);
    const int tid = threadIdx.x, lane = tid & 31, warp = tid >> 5;
    const int wm = warp >> 2, wn = warp & 3;
    const int which = blockIdx.z % 3;
    const int b = blockIdx.z / 3;
    const int oT = blockIdx.y * 128, nT = blockIdx.x * 128;

    const __half* Wh = g_wh + (size_t)which*NC*NC;
    const __half* Xh = g_xh + (size_t)b*NC*NN;
    const float* bias = (which==0) ? bq : (which==1) ? bk : bv;
    __half* Oh = (which==0) ? g_qh : (which==1) ? g_kh : g_vh;

    auto aAddr = [&](int buf,int row,int u)->uint32_t{
        return sbase + (uint32_t)(buf*512 + row*4 + (u ^ ((row>>1)&3)))*16u; };
    auto bAddr = [&](int buf,int row,int u)->uint32_t{
        return sbase + (uint32_t)(1024 + buf*512 + row*16 + (u ^ (row&7)))*16u; };

    auto issue = [&](int ct, int buf){
        #pragma unroll
        for (int s = 0; s < 2; s++){
            int idx = tid + (s<<8);
            int row = idx >> 2, u = idx & 3;
            cp16(aAddr(buf,row,u), Wh + (size_t)(oT+row)*NC + ct + u*8);
        }
        #pragma unroll
        for (int s = 0; s < 2; s++){
            int idx = tid + (s<<8);
            int row = idx >> 4, u = idx & 15;
            cp16(bAddr(buf,row,u), Xh + (size_t)(ct+row)*NN + nT + u*8);
        }
    };

    float C[4][4][4];
    #pragma unroll
    for (int a=0;a<4;a++)
        #pragma unroll
        for (int bb=0;bb<4;bb++)
            #pragma unroll
            for (int c=0;c<4;c++) C[a][bb][c]=0.f;

    issue(0, 0); cp_commit();
    for (int it = 0; it < 16; it++){
        if (it < 15){ issue((it+1)*32, (it+1)&1); cp_commit(); cp_wait<1>(); }
        else        { cp_wait<0>(); }
        __syncthreads();
        int buf = it & 1;
        #pragma unroll
        for (int k16 = 0; k16 < 2; k16++){
            int kk = k16 << 4;
            uint32_t ah[4][4], bh[4][2];
            #pragma unroll
            for (int mi = 0; mi < 4; mi++){
                int row = wm*64 + mi*16 + (lane & 15);
                int kg  = (kk >> 3) + (lane >> 4);
                ldsm4(ah[mi], aAddr(buf,row,kg));
            }
            #pragma unroll
            for (int ni = 0; ni < 4; ni++){
                int row = kk + (lane & 15);
                int u = wn*4 + ni;
                ldsm2t(bh[ni], bAddr(buf,row,u));
            }
            #pragma unroll
            for (int mi = 0; mi < 4; mi++)
                #pragma unroll
                for (int ni = 0; ni < 4; ni++)
                    mma_f16(C[mi][ni], ah[mi], bh[ni]);
        }
        __syncthreads();
    }
    #pragma unroll
    for (int mi = 0; mi < 4; mi++){
        int r0 = oT + wm*64 + mi*16 + (lane >> 2);
        float bi0 = bias[r0], bi1 = bias[r0 + 8];
        #pragma unroll
        for (int ni = 0; ni < 4; ni++){
            int c0 = nT + wn*32 + ni*8 + (lane & 3)*2;
            size_t o0 = ((size_t)b*NC + r0)*NN + c0;
            *reinterpret_cast<__half2*>(Oh + o0) =
                __floats2half2_rn(C[mi][ni][0]+bi0, C[mi][ni][1]+bi0);
            *reinterpret_cast<__half2*>(Oh + o0 + (size_t)8*NN) =
                __floats2half2_rn(C[mi][ni][2]+bi1, C[mi][ni][3]+bi1);
        }
    }
}

// ---------------- attention: flash-style + online max, fp16, BM=128, BN=64 ----------------
// smem 16B-units: Q' [0,2048): r*16+(u^(r&7)); K' 2048+buf*1024+r*8+(u^(r&7));
// V 4096+buf*512+r*8+(u^(r&7)).  Total 5120 units = 80KB -> 2 CTAs/SM.
__global__ __launch_bounds__(256, 2) void attn_mma_kernel(const float* __restrict__ x,
                                                          float* __restrict__ out)
{
    extern __shared__ uint4 smemraw[];
    const uint32_t sbase = (uint32_t)__cvta_generic_to_shared(smemraw);
    float* smf = reinterpret_cast<float*>(smemraw);
    const int tid = threadIdx.x, lane = tid & 31, warp = tid >> 5;
    const int wm = warp >> 1, wn = warp & 1;
    const int b = blockIdx.z, h = blockIdx.y;
    const int i0 = blockIdx.x * 128;
    const size_t qoff = ((size_t)b*NC + h*ND)*NN;

    auto loadQ = [&](){
        #pragma unroll
        for (int s = 0; s < 8; s++){
            int idx = tid + s*256;
            int r = idx >> 4, u = idx & 15;
            const __half* src = (r < 64)
                ? g_qh + qoff + (size_t)r*NN + i0 + u*8
                : g_ph + ((size_t)h*ND + (r-64))*NN + i0 + u*8;
            cp16(sbase + (uint32_t)(r*16 + (u ^ (r&7)))*16u, src);
        }
    };
    auto loadKV = [&](int jt, int buf){
        int j0 = jt * 64;
        #pragma unroll
        for (int s = 0; s < 4; s++){
            int idx = tid + s*256;
            int r = idx >> 3, u = idx & 7;
            const __half* src = (r < 64)
                ? g_kh + qoff + (size_t)r*NN + j0 + u*8
                : g_qh + qoff + (size_t)(r-64)*NN + j0 + u*8;
            cp16(sbase + (uint32_t)(2048 + buf*1024 + r*8 + (u ^ (r&7)))*16u, src);
        }
        #pragma unroll
        for (int s = 0; s < 2; s++){
            int idx = tid + s*256;
            int r = idx >> 3, u = idx & 7;
            const __half* src = g_vh + qoff + (size_t)r*NN + j0 + u*8;
            cp16(sbase + (uint32_t)(4096 + buf*512 + r*8 + (u ^ (r&7)))*16u, src);
        }
    };

    float Oc[2][8][4];
    #pragma unroll
    for (int a=0;a<2;a++)
        #pragma unroll
        for (int bb=0;bb<8;bb++)
            #pragma unroll
            for (int c=0;c<4;c++) Oc[a][bb][c]=0.f;
    float rs[2][2] = {{0.f,0.f},{0.f,0.f}};
    float mr[2][2] = {{-1e30f,-1e30f},{-1e30f,-1e30f}};

    loadQ(); loadKV(0, 0); cp_commit();

    for (int jt = 0; jt < 16; jt++){
        if (jt < 15){ loadKV(jt+1, (jt+1)&1); cp_commit(); cp_wait<1>(); }
        else        { cp_wait<0>(); }
        __syncthreads();
        int buf = jt & 1;

        // ---- S = Q'^T K' (k=128, 8 k16 steps, fp16 single-term) ----
        float S[2][4][4];
        #pragma unroll
        for (int a=0;a<2;a++)
            #pragma unroll
            for (int bb=0;bb<4;bb++)
                #pragma unroll
                for (int c=0;c<4;c++) S[a][bb][c]=0.f;

        #pragma unroll
        for (int k16 = 0; k16 < 8; k16++){
            uint32_t aH[2][4], bH[4][2];
            int arow = k16*16 + (lane & 7) + ((lane >> 4) << 3);
            #pragma unroll
            for (int mi = 0; mi < 2; mi++){
                int au = wm*4 + mi*2 + ((lane >> 3) & 1);
                ldsm4t(aH[mi], sbase + (uint32_t)(arow*16 + (au ^ (arow&7)))*16u);
            }
            int brow = k16*16 + (lane & 15);
            #pragma unroll
            for (int ni = 0; ni < 4; ni++){
                int bu = wn*4 + ni;
                ldsm2t(bH[ni], sbase + (uint32_t)(2048 + buf*1024 + brow*8 + (bu ^ (brow&7)))*16u);
            }
            #pragma unroll
            for (int mi = 0; mi < 2; mi++)
                #pragma unroll
                for (int ni = 0; ni < 4; ni++)
                    mma_f16(S[mi][ni], aH[mi], bH[ni]);
        }

        // ---- online softmax (per-warp running max over its j-half) ----
        #pragma unroll
        for (int mi = 0; mi < 2; mi++){
            float t0 = -1e30f, t1 = -1e30f;
            #pragma unroll
            for (int ni = 0; ni < 4; ni++){
                t0 = fmaxf(t0, fmaxf(S[mi][ni][0], S[mi][ni][1]));
                t1 = fmaxf(t1, fmaxf(S[mi][ni][2], S[mi][ni][3]));
            }
            #pragma unroll
            for (int off = 1; off < 4; off <<= 1){
                t0 = fmaxf(t0, __shfl_xor_sync(0xffffffffu, t0, off));
                t1 = fmaxf(t1, __shfl_xor_sync(0xffffffffu, t1, off));
            }
            float nm0 = fmaxf(mr[mi][0], t0), nm1 = fmaxf(mr[mi][1], t1);
            float sc0 = __expf(mr[mi][0] - nm0), sc1 = __expf(mr[mi][1] - nm1);
            mr[mi][0] = nm0; mr[mi][1] = nm1;
            float ps0 = 0.f, ps1 = 0.f;
            #pragma unroll
            for (int ni = 0; ni < 4; ni++){
                S[mi][ni][0] = __expf(S[mi][ni][0] - nm0);
                S[mi][ni][1] = __expf(S[mi][ni][1] - nm0);
                S[mi][ni][2] = __expf(S[mi][ni][2] - nm1);
                S[mi][ni][3] = __expf(S[mi][ni][3] - nm1);
                ps0 += S[mi][ni][0] + S[mi][ni][1];
                ps1 += S[mi][ni][2] + S[mi][ni][3];
            }
            rs[mi][0] = rs[mi][0]*sc0 + ps0;
            rs[mi][1] = rs[mi][1]*sc1 + ps1;
            #pragma unroll
            for (int nd = 0; nd < 8; nd++){
                Oc[mi][nd][0] *= sc0; Oc[mi][nd][1] *= sc0;
                Oc[mi][nd][2] *= sc1; Oc[mi][nd][3] *= sc1;
            }
        }

        // ---- O += P V^T (P in regs as fp16 A-fragments; V from smem) ----
        #pragma unroll
        for (int kt = 0; kt < 2; kt++){
            uint32_t pF[2][4];
            #pragma unroll
            for (int mi = 0; mi < 2; mi++){
                pF[mi][0] = packh2(S[mi][2*kt  ][0], S[mi][2*kt  ][1]);
                pF[mi][1] = packh2(S[mi][2*kt  ][2], S[mi][2*kt  ][3]);
                pF[mi][2] = packh2(S[mi][2*kt+1][0], S[mi][2*kt+1][1]);
                pF[mi][3] = packh2(S[mi][2*kt+1][2], S[mi][2*kt+1][3]);
            }
            #pragma unroll
            for (int nd = 0; nd < 8; nd++){
                int vrow = nd*8 + (lane & 7);
                int vu = wn*4 + kt*2 + ((lane >> 3) & 1);
                uint32_t vF[2];
                ldsm2(vF, sbase + (uint32_t)(4096 + buf*512 + vrow*8 + (vu ^ (vrow&7)))*16u);
                #pragma unroll
                for (int mi = 0; mi < 2; mi++)
                    mma_f16(Oc[mi][nd], pF[mi], vF);
            }
        }
        __syncthreads();
    }

    // ---- cross-warp combine (max reconciliation), normalize, +x, store ----
    float* Os = smf;                   // [128 i][65] fp32 (tiles dead now)
    float* rsum_s = smf + 128*65;      // [128]
    float* mmax_s = rsum_s + 128;      // [128]
    #pragma unroll
    for (int off = 1; off < 4; off <<= 1)
        #pragma unroll
        for (int mi = 0; mi < 2; mi++){
            rs[mi][0] += __shfl_xor_sync(0xffffffffu, rs[mi][0], off);
            rs[mi][1] += __shfl_xor_sync(0xffffffffu, rs[mi][1], off);
        }
    if (wn == 0){
        #pragma unroll
        for (int mi = 0; mi < 2; mi++){
            int ib = wm*32 + mi*16 + (lane >> 2);
            #pragma unroll
            for (int nd = 0; nd < 8; nd++){
                int dd = nd*8 + (lane & 3)*2;
                Os[ib*65 + dd]       = Oc[mi][nd][0];
                Os[ib*65 + dd + 1]   = Oc[mi][nd][1];
                Os[(ib+8)*65 + dd]   = Oc[mi][nd][2];
                Os[(ib+8)*65 + dd+1] = Oc[mi][nd][3];
            }
            if ((lane & 3) == 0){
                rsum_s[ib]   = rs[mi][0]; rsum_s[ib+8] = rs[mi][1];
                mmax_s[ib]   = mr[mi][0]; mmax_s[ib+8] = mr[mi][1];
            }
        }
    }
    __syncthreads();
    if (wn == 1){
        #pragma unroll
        for (int mi = 0; mi < 2; mi++){
            int ib = wm*32 + mi*16 + (lane >> 2);
            float m0a = mmax_s[ib], m0b = mmax_s[ib+8];
            float Ma = fmaxf(m0a, mr[mi][0]), Mb = fmaxf(m0b, mr[mi][1]);
            float s0a = __expf(m0a - Ma), s1a = __expf(mr[mi][0] - Ma);
            float s0b = __expf(m0b - Mb), s1b = __expf(mr[mi][1] - Mb);
            #pragma unroll
            for (int nd = 0; nd < 8; nd++){
                int dd = nd*8 + (lane & 3)*2;
                Os[ib*65 + dd]       = Os[ib*65 + dd]      *s0a + Oc[mi][nd][0]*s1a;
                Os[ib*65 + dd + 1]   = Os[ib*65 + dd + 1]  *s0a + Oc[mi][nd][1]*s1a;
                Os[(ib+8)*65 + dd]   = Os[(ib+8)*65 + dd]  *s0b + Oc[mi][nd][2]*s1b;
                Os[(ib+8)*65 + dd+1] = Os[(ib+8)*65 + dd+1]*s0b + Oc[mi][nd][3]*s1b;
            }
            if ((lane & 3) == 0){
                rsum_s[ib]   = rsum_s[ib]  *s0a + rs[mi][0]*s1a;
                rsum_s[ib+8] = rsum_s[ib+8]*s0b + rs[mi][1]*s1b;
            }
        }
    }
    __syncthreads();
    if (tid < 128) rsum_s[tid] = 1.0f / rsum_s[tid];
    __syncthreads();

    const float* xb = x + qoff;
    float* ob = out + qoff;
    #pragma unroll
    for (int s = 0; s < 32; s++){
        int idx = tid + s*256;
        int dd = idx >> 7, iL = idx & 127;
        ob[(size_t)dd*NN + i0 + iL] =
            Os[iL*65 + dd] * rsum_s[iL] + xb[(size_t)dd*NN + i0 + iL];
    }
}

extern "C" void kernel_launch(void* const* d_in, const int* in_sizes, int n_in,
                              void* d_out, int out_size) {
    (void)in_sizes; (void)n_in; (void)out_size;
    const float* x     = (const float*)d_in[0];
    const float* Wq    = (const float*)d_in[1];
    const float* bq    = (const float*)d_in[2];
    const float* Wk    = (const float*)d_in[3];
    const float* bk    = (const float*)d_in[4];
    const float* Wv    = (const float*)d_in[5];
    const float* bv    = (const float*)d_in[6];
    const float* rel_h = (const float*)d_in[7];
    const float* rel_w = (const float*)d_in[8];
    // d_in[9]/d_in[10] (reg_qk/reg_v) are provably dead: the reg group is sliced
    // away by out[:, :head] and softmax/PV are group-independent.
    float* out = (float*)d_out;

    cudaFuncSetAttribute(qkv_mma_kernel,
        cudaFuncAttributeMaxDynamicSharedMemorySize, 32768);
    cudaFuncSetAttribute(attn_mma_kernel,
        cudaFuncAttributeMaxDynamicSharedMemorySize, 81920);

    cvt_kernel<<<8192, 256>>>(x,  0, 0, 2097152);
    cvt_kernel<<<256, 256>>>(Wq, 1, 0, 65536);
    cvt_kernel<<<256, 256>>>(Wk, 1, (size_t)NC*NC, 65536);
    cvt_kernel<<<256, 256>>>(Wv, 1, (size_t)2*NC*NC, 65536);
    pos_cvt_kernel<<<2048, 256>>>(rel_h, rel_w);
    qkv_mma_kernel<<<dim3(NN/128, NC/128, 3*NB), 256, 32768>>>(bq, bk, bv);
    attn_mma_kernel<<<dim3(NN/128, NH, NB), 256, 81920>>>(x, out);
}